// round 2
// baseline (speedup 1.0000x reference)
#include <cuda_runtime.h>

#define MAX_N 50000
#define MAX_E 800000
#define HDIM  64

// ---------------- scratch (no allocations allowed) ----------------
__device__ float g_tx[2L * MAX_N * HDIM];   // per-relation transformed features
__device__ float g_bufA[MAX_N * HDIM];
__device__ float g_bufB[MAX_N * HDIM];
__device__ float g_ev[2L * MAX_N * 2];      // layer-3 per-relation messages
__device__ int   g_cnt[MAX_N];
__device__ int   g_off[MAX_N + 1];
__device__ int   g_pos[MAX_N];
__device__ unsigned g_elist[MAX_E];         // packed: src | (etype<<16)
__device__ unsigned int g_min_key;

// monotone float<->uint encoding so atomicMin(uint) == float min
__device__ __forceinline__ unsigned fenc(float f) {
    unsigned b = __float_as_uint(f);
    return (b & 0x80000000u) ? ~b : (b | 0x80000000u);
}
__device__ __forceinline__ float fdec(unsigned k) {
    unsigned b = (k & 0x80000000u) ? (k ^ 0x80000000u) : ~k;
    return __uint_as_float(b);
}

// ================= CSR build =================
__global__ void zero_cnt_kernel(int N) {
    int i = blockIdx.x * blockDim.x + threadIdx.x;
    if (i < N) g_cnt[i] = 0;
}

__global__ void hist_kernel(const int* __restrict__ dst, int E) {
    int e = blockIdx.x * blockDim.x + threadIdx.x;
    if (e < E) atomicAdd(&g_cnt[dst[e]], 1);
}

// single-block chunked exclusive scan over N counts -> g_off / g_pos
__global__ void __launch_bounds__(1024) scan_kernel(int N) {
    __shared__ int sa[1024], sb[1024];
    const int tid = threadIdx.x;
    const int chunk = (N + 1023) / 1024;
    const int base = tid * chunk;
    const int lim = min(base + chunk, N);

    int sum = 0;
    for (int i = base; i < lim; i++) sum += g_cnt[i];

    sa[tid] = sum;
    __syncthreads();
    int* in = sa; int* out = sb;
    #pragma unroll
    for (int o = 1; o < 1024; o <<= 1) {
        out[tid] = in[tid] + (tid >= o ? in[tid - o] : 0);
        __syncthreads();
        int* t = in; in = out; out = t;
    }
    int run = in[tid] - sum;   // exclusive prefix
    for (int i = base; i < lim; i++) {
        g_off[i] = run; g_pos[i] = run;
        run += g_cnt[i];
    }
    if (tid == 1023) g_off[N] = in[1023];
}

__global__ void fill_kernel(const int* __restrict__ src,
                            const int* __restrict__ dst,
                            const int* __restrict__ et, int E) {
    int e = blockIdx.x * blockDim.x + threadIdx.x;
    if (e >= E) return;
    int p = atomicAdd(&g_pos[dst[e]], 1);
    g_elist[p] = (unsigned)src[e] | ((unsigned)et[e] << 16);
}

// ================= fused triple GEMM =================
// {C0,C1,Cl} = relu?(A) @ {W0,W1,Wl}(+bias). blockIdx.y selects weight.
template<bool RELU_IN>
__global__ void __launch_bounds__(256) gemm3_kernel(
    const float* __restrict__ A, int M, int K,
    const float* __restrict__ W0, const float* __restrict__ W1,
    const float* __restrict__ Wl, const float* __restrict__ bias,
    float* __restrict__ C0, float* __restrict__ C1, float* __restrict__ Cl)
{
    constexpr int BM = 128, BN = 64, BK = 32;
    __shared__ float As[BK][BM];
    __shared__ float Bs[BK][BN];

    const float* W;
    float* C;
    bool use_bias = false;
    if      (blockIdx.y == 0) { W = W0; C = C0; }
    else if (blockIdx.y == 1) { W = W1; C = C1; }
    else                      { W = Wl; C = Cl; use_bias = true; }

    const int tid = threadIdx.x;
    const int tn = tid & 15;
    const int tm = tid >> 4;
    const int rowBase = blockIdx.x * BM;

    float acc[8][4];
    #pragma unroll
    for (int i = 0; i < 8; i++)
        #pragma unroll
        for (int j = 0; j < 4; j++) acc[i][j] = 0.f;

    for (int k0 = 0; k0 < K; k0 += BK) {
        #pragma unroll
        for (int it = 0; it < 4; it++) {
            int f4 = tid + it * 256;
            int r  = f4 >> 3;
            int kq = (f4 & 7) << 2;
            float4 v = make_float4(0.f, 0.f, 0.f, 0.f);
            int grow = rowBase + r;
            if (grow < M) {
                v = *(const float4*)&A[(long)grow * K + k0 + kq];
                if (RELU_IN) {
                    v.x = fmaxf(v.x, 0.f); v.y = fmaxf(v.y, 0.f);
                    v.z = fmaxf(v.z, 0.f); v.w = fmaxf(v.w, 0.f);
                }
            }
            As[kq + 0][r] = v.x; As[kq + 1][r] = v.y;
            As[kq + 2][r] = v.z; As[kq + 3][r] = v.w;
        }
        #pragma unroll
        for (int it = 0; it < 2; it++) {
            int f4 = tid + it * 256;
            int kk = f4 >> 4;
            int nq = (f4 & 15) << 2;
            *(float4*)&Bs[kk][nq] = *(const float4*)&W[(long)(k0 + kk) * BN + nq];
        }
        __syncthreads();

        #pragma unroll
        for (int kk = 0; kk < BK; kk++) {
            float4 a0 = *(const float4*)&As[kk][tm * 8];
            float4 a1 = *(const float4*)&As[kk][tm * 8 + 4];
            float4 b  = *(const float4*)&Bs[kk][tn * 4];
            float av[8] = {a0.x, a0.y, a0.z, a0.w, a1.x, a1.y, a1.z, a1.w};
            float bv[4] = {b.x, b.y, b.z, b.w};
            #pragma unroll
            for (int i = 0; i < 8; i++)
                #pragma unroll
                for (int j = 0; j < 4; j++)
                    acc[i][j] = fmaf(av[i], bv[j], acc[i][j]);
        }
        __syncthreads();
    }

    float4 bb = make_float4(0.f, 0.f, 0.f, 0.f);
    if (use_bias) bb = *(const float4*)&bias[tn * 4];
    #pragma unroll
    for (int i = 0; i < 8; i++) {
        int grow = rowBase + tm * 8 + i;
        if (grow < M) {
            float4 o;
            o.x = acc[i][0] + bb.x; o.y = acc[i][1] + bb.y;
            o.z = acc[i][2] + bb.z; o.w = acc[i][3] + bb.w;
            *(float4*)&C[(long)grow * BN + tn * 4] = o;
        }
    }
}

// ================= gather aggregation (no atomics) =================
// one warp per node: agg[n] += sum over incoming edges of t[etype][src]
__global__ void gather64_kernel(const float* __restrict__ t,
                                float* __restrict__ agg, int N)
{
    int warp = (int)((blockIdx.x * (long)blockDim.x + threadIdx.x) >> 5);
    int lane = threadIdx.x & 31;
    if (warp >= N) return;
    int beg = g_off[warp], end = g_off[warp + 1];
    long o = (long)warp * 64 + lane * 2;
    float2 acc = *(float2*)&agg[o];
    for (int e = beg; e < end; e++) {
        unsigned p = g_elist[e];
        long s  = p & 0xFFFFu;
        long et = p >> 16;
        float2 v = *(const float2*)&t[(et * N + s) * 64 + lane * 2];
        acc.x += v.x; acc.y += v.y;
    }
    *(float2*)&agg[o] = acc;
}

// one thread per node for the 2-wide final layer
__global__ void gather2_kernel(const float* __restrict__ ev,
                               float* __restrict__ out, int N)
{
    int n = blockIdx.x * blockDim.x + threadIdx.x;
    if (n >= N) return;
    int beg = g_off[n], end = g_off[n + 1];
    float2 acc = *(float2*)&out[n * 2];
    for (int e = beg; e < end; e++) {
        unsigned p = g_elist[e];
        long s  = p & 0xFFFFu;
        long et = p >> 16;
        float2 v = *(const float2*)&ev[(et * N + s) * 2];
        acc.x += v.x; acc.y += v.y;
    }
    *(float2*)&out[n * 2] = acc;
}

// ================= layer 3 per-node transforms =================
__global__ void layer3_kernel(
    const float* __restrict__ H,
    const float* __restrict__ W3, const float* __restrict__ L3,
    const float* __restrict__ b3,
    float* __restrict__ ev, float* __restrict__ out, int N)
{
    __shared__ float sW0[128], sW1[128], sL[128], sb[2];
    int tid = threadIdx.x;
    for (int i = tid; i < 128; i += blockDim.x) {
        sW0[i] = W3[i];
        sW1[i] = W3[128 + i];
        sL[i]  = L3[i];
    }
    if (tid < 2) sb[tid] = b3[tid];
    __syncthreads();

    int n = blockIdx.x * blockDim.x + tid;
    if (n >= N) return;
    const float* h = &H[(long)n * 64];
    float a0 = 0.f, a1 = 0.f, c0 = 0.f, c1 = 0.f, l0 = 0.f, l1 = 0.f;
    #pragma unroll
    for (int k = 0; k < 64; k += 4) {
        float4 hv = *(const float4*)&h[k];
        float xv[4] = {fmaxf(hv.x, 0.f), fmaxf(hv.y, 0.f),
                       fmaxf(hv.z, 0.f), fmaxf(hv.w, 0.f)};
        #pragma unroll
        for (int j = 0; j < 4; j++) {
            int kk = k + j;
            a0 = fmaf(xv[j], sW0[kk * 2 + 0], a0);
            a1 = fmaf(xv[j], sW0[kk * 2 + 1], a1);
            c0 = fmaf(xv[j], sW1[kk * 2 + 0], c0);
            c1 = fmaf(xv[j], sW1[kk * 2 + 1], c1);
            l0 = fmaf(xv[j], sL[kk * 2 + 0], l0);
            l1 = fmaf(xv[j], sL[kk * 2 + 1], l1);
        }
    }
    *(float2*)&ev[n * 2] = make_float2(a0, a1);
    *(float2*)&ev[((long)N + n) * 2] = make_float2(c0, c1);
    *(float2*)&out[n * 2] = make_float2(l0 + sb[0], l1 + sb[1]);
}

// ================= global min + mask =================
__global__ void init_min_kernel() { g_min_key = 0xFFFFFFFFu; }

__global__ void min_kernel(const float* __restrict__ v, int n)
{
    float m = 3.402823466e+38f;
    for (int i = blockIdx.x * blockDim.x + threadIdx.x; i < n;
         i += gridDim.x * blockDim.x)
        m = fminf(m, v[i]);
    #pragma unroll
    for (int o = 16; o; o >>= 1)
        m = fminf(m, __shfl_xor_sync(0xffffffffu, m, o));
    __shared__ float sm[8];
    if ((threadIdx.x & 31) == 0) sm[threadIdx.x >> 5] = m;
    __syncthreads();
    if (threadIdx.x < 8) {
        m = sm[threadIdx.x];
        #pragma unroll
        for (int o = 4; o; o >>= 1)
            m = fminf(m, __shfl_xor_sync(0xffu, m, o));
        if (threadIdx.x == 0) atomicMin(&g_min_key, fenc(m));
    }
}

__global__ void mask_kernel(float* __restrict__ out,
                            const int* __restrict__ cs,
                            const int* __restrict__ ms, int N)
{
    int n = blockIdx.x * blockDim.x + threadIdx.x;
    if (n >= N) return;
    float mn = fdec(g_min_key) - 1.0f;
    float2 v = *(float2*)&out[n * 2];
    if (cs[n] >= ms[n] - 1) v.x = mn;
    if (cs[n] == 0)         v.y = mn;
    *(float2*)&out[n * 2] = v;
}

// ================= launch =================
extern "C" void kernel_launch(void* const* d_in, const int* in_sizes, int n_in,
                              void* d_out, int out_size)
{
    const float* x  = (const float*)d_in[0];
    const int* src  = (const int*)d_in[1];
    const int* dst  = (const int*)d_in[2];
    const int* et   = (const int*)d_in[3];
    const int* cs   = (const int*)d_in[4];
    const int* ms   = (const int*)d_in[5];
    const float* W1 = (const float*)d_in[6];
    const float* L1 = (const float*)d_in[7];
    const float* b1 = (const float*)d_in[8];
    const float* W2 = (const float*)d_in[9];
    const float* L2 = (const float*)d_in[10];
    const float* b2 = (const float*)d_in[11];
    const float* W3 = (const float*)d_in[12];
    const float* L3 = (const float*)d_in[13];
    const float* b3 = (const float*)d_in[14];

    const int N = in_sizes[0] / 128;
    const int E = in_sizes[1];
    float* out = (float*)d_out;

    float *tx, *bufA, *bufB, *ev;
    cudaGetSymbolAddress((void**)&tx,   g_tx);
    cudaGetSymbolAddress((void**)&bufA, g_bufA);
    cudaGetSymbolAddress((void**)&bufB, g_bufB);
    cudaGetSymbolAddress((void**)&ev,   g_ev);

    dim3 gemm_grid((N + 127) / 128, 3);
    int nodeBlocks = (N + 255) / 256;
    int edgeBlocks = (E + 255) / 256;
    int gatherBlocks = (N * 32 + 255) / 256;

    // --- CSR build (reused by all 3 aggregations) ---
    zero_cnt_kernel<<<nodeBlocks, 256>>>(N);
    hist_kernel<<<edgeBlocks, 256>>>(dst, E);
    scan_kernel<<<1, 1024>>>(N);
    fill_kernel<<<edgeBlocks, 256>>>(src, dst, et, E);

    // --- layer 1 ---
    gemm3_kernel<false><<<gemm_grid, 256>>>(x, N, 128,
        W1, W1 + 128 * 64, L1, b1, tx, tx + (long)N * 64, bufA);
    gather64_kernel<<<gatherBlocks, 256>>>(tx, bufA, N);

    // --- layer 2 ---
    gemm3_kernel<true><<<gemm_grid, 256>>>(bufA, N, 64,
        W2, W2 + 64 * 64, L2, b2, tx, tx + (long)N * 64, bufB);
    gather64_kernel<<<gatherBlocks, 256>>>(tx, bufB, N);

    // --- layer 3 ---
    layer3_kernel<<<nodeBlocks, 256>>>(bufB, W3, L3, b3, ev, out, N);
    gather2_kernel<<<nodeBlocks, 256>>>(ev, out, N);

    // --- global min then action mask ---
    init_min_kernel<<<1, 1>>>();
    min_kernel<<<160, 256>>>(out, N * 2);
    mask_kernel<<<nodeBlocks, 256>>>(out, cs, ms, N);
}

// round 3
// speedup vs baseline: 1.3742x; 1.3742x over previous
#include <cuda_runtime.h>
#include <cuda_bf16.h>
#include <cstdint>

#define MAX_N 50000
#define HDIM  64

// ---------------- scratch (no allocations allowed) ----------------
__device__ float g_tx0[MAX_N * HDIM];
__device__ float g_tx1[MAX_N * HDIM];
__device__ float g_bufA[MAX_N * HDIM];
__device__ float g_bufB[MAX_N * HDIM];
__device__ float g_e0[MAX_N * 2];
__device__ float g_e1[MAX_N * 2];
__device__ unsigned int g_min_key;

// monotone float<->uint encoding so atomicMin(uint) == float min
__device__ __forceinline__ unsigned fenc(float f) {
    unsigned b = __float_as_uint(f);
    return (b & 0x80000000u) ? ~b : (b | 0x80000000u);
}
__device__ __forceinline__ float fdec(unsigned k) {
    unsigned b = (k & 0x80000000u) ? (k ^ 0x80000000u) : ~k;
    return __uint_as_float(b);
}

// ---------------- tensor-core helpers ----------------
__device__ __forceinline__ void ldsm_x4(uint32_t* r, const void* p) {
    uint32_t a = (uint32_t)__cvta_generic_to_shared(p);
    asm volatile("ldmatrix.sync.aligned.m8n8.x4.shared.b16 {%0,%1,%2,%3}, [%4];"
        : "=r"(r[0]), "=r"(r[1]), "=r"(r[2]), "=r"(r[3]) : "r"(a));
}
__device__ __forceinline__ void ldsm_x2t(uint32_t* r, const void* p) {
    uint32_t a = (uint32_t)__cvta_generic_to_shared(p);
    asm volatile("ldmatrix.sync.aligned.m8n8.x2.trans.shared.b16 {%0,%1}, [%2];"
        : "=r"(r[0]), "=r"(r[1]) : "r"(a));
}
__device__ __forceinline__ void mma_bf16(float* c, const uint32_t* a, const uint32_t* b) {
    asm volatile("mma.sync.aligned.m16n8k16.row.col.f32.bf16.bf16.f32 "
        "{%0,%1,%2,%3}, {%4,%5,%6,%7}, {%8,%9}, {%0,%1,%2,%3};"
        : "+f"(c[0]), "+f"(c[1]), "+f"(c[2]), "+f"(c[3])
        : "r"(a[0]), "r"(a[1]), "r"(a[2]), "r"(a[3]), "r"(b[0]), "r"(b[1]));
}
__device__ __forceinline__ void split_bf16(float v, __nv_bfloat16& h, __nv_bfloat16& l) {
    h = __float2bfloat16(v);
    l = __float2bfloat16(v - __bfloat162float(h));
}

// ---------------- tensor-core triple GEMM ----------------
// {C0,C1,Cl} = relu?(A[M,K]) @ {W0,W1,Wl}[K,64] (+bias on Cl).
// One CTA: 64 rows x 192 output cols (3 weights). Split-bf16 for fp32 accuracy.
template<int K, bool RELU_IN>
__global__ void __launch_bounds__(256) gemm_tc_kernel(
    const float* __restrict__ A, int M,
    const float* __restrict__ W0, const float* __restrict__ W1,
    const float* __restrict__ Wl, const float* __restrict__ bias,
    float* __restrict__ C0, float* __restrict__ C1, float* __restrict__ Cl)
{
    constexpr int BM = 64;
    constexpr int AS = K + 8;   // A smem row stride (bf16 elems) -> conflict-free ldsm
    constexpr int WS = 72;      // W smem row stride
    extern __shared__ __nv_bfloat16 sm[];
    __nv_bfloat16* Ahi = sm;                    // [BM][AS]
    __nv_bfloat16* Alo = Ahi + BM * AS;
    __nv_bfloat16* Whi = Alo + BM * AS;         // [3][K][WS]
    __nv_bfloat16* Wlo = Whi + 3 * K * WS;

    const int tid  = threadIdx.x;
    const int lane = tid & 31;
    const int warp = tid >> 5;
    const int rowBase = blockIdx.x * BM;

    // ---- load & split weights (all 3) ----
    const float* Ws[3] = {W0, W1, Wl};
    #pragma unroll
    for (int w = 0; w < 3; w++) {
        const float* Wp = Ws[w];
        for (int i = tid * 4; i < K * 64; i += 256 * 4) {
            float4 v = *(const float4*)&Wp[i];
            int k = i >> 6, n = i & 63;
            float vv[4] = {v.x, v.y, v.z, v.w};
            #pragma unroll
            for (int j = 0; j < 4; j++) {
                __nv_bfloat16 h, l;
                split_bf16(vv[j], h, l);
                Whi[(w * K + k) * WS + n + j] = h;
                Wlo[(w * K + k) * WS + n + j] = l;
            }
        }
    }

    // ---- load & split A tile ----
    for (int i = tid * 4; i < BM * K; i += 256 * 4) {
        int r = i / K, kq = i % K;
        float4 v = make_float4(0.f, 0.f, 0.f, 0.f);
        if (rowBase + r < M) v = *(const float4*)&A[(long)(rowBase + r) * K + kq];
        float vv[4] = {v.x, v.y, v.z, v.w};
        #pragma unroll
        for (int j = 0; j < 4; j++) {
            float x = RELU_IN ? fmaxf(vv[j], 0.f) : vv[j];
            __nv_bfloat16 h, l;
            split_bf16(x, h, l);
            Ahi[r * AS + kq + j] = h;
            Alo[r * AS + kq + j] = l;
        }
    }
    __syncthreads();

    // ---- warp tiling: 4 warps in M (16 each), 2 warps in N (96 each) ----
    const int mw = (warp & 3) * 16;
    const int nw = (warp >> 2) * 96;

    float acc[12][4];
    #pragma unroll
    for (int j = 0; j < 12; j++)
        #pragma unroll
        for (int q = 0; q < 4; q++) acc[j][q] = 0.f;

    const int aRow = mw + (lane & 15);
    const int aCol = (lane >> 4) * 8;
    const int bRow = lane & 15;

    #pragma unroll
    for (int kk = 0; kk < K / 16; kk++) {
        uint32_t ah[4], al[4];
        ldsm_x4(ah, &Ahi[aRow * AS + kk * 16 + aCol]);
        ldsm_x4(al, &Alo[aRow * AS + kk * 16 + aCol]);
        #pragma unroll
        for (int j = 0; j < 12; j++) {
            int n = nw + j * 8;
            int w = n >> 6, nc = n & 63;
            long woff = (long)(w * K + kk * 16 + bRow) * WS + nc;
            uint32_t bh[2], bl[2];
            ldsm_x2t(bh, &Whi[woff]);
            ldsm_x2t(bl, &Wlo[woff]);
            mma_bf16(acc[j], ah, bh);   // hi*hi
            mma_bf16(acc[j], ah, bl);   // hi*lo
            mma_bf16(acc[j], al, bh);   // lo*hi
        }
    }

    // ---- epilogue ----
    float* Cs[3] = {C0, C1, Cl};
    const int r0 = rowBase + mw + (lane >> 2);
    #pragma unroll
    for (int j = 0; j < 12; j++) {
        int n = nw + j * 8;
        int w = n >> 6;
        int nc = (n & 63) + 2 * (lane & 3);
        float b0 = 0.f, b1 = 0.f;
        if (w == 2) { b0 = bias[nc]; b1 = bias[nc + 1]; }
        if (r0 < M)
            *(float2*)&Cs[w][(long)r0 * 64 + nc] =
                make_float2(acc[j][0] + b0, acc[j][1] + b1);
        if (r0 + 8 < M)
            *(float2*)&Cs[w][(long)(r0 + 8) * 64 + nc] =
                make_float2(acc[j][2] + b0, acc[j][3] + b1);
    }
}

// ---------------- edge scatter: agg[dst] += tx[etype][src], 64 floats ----------------
__global__ void scatter64_kernel(
    const float* __restrict__ t0, const float* __restrict__ t1,
    const int* __restrict__ src, const int* __restrict__ dst,
    const int* __restrict__ et, float* __restrict__ agg, int E)
{
    long idx = (long)blockIdx.x * blockDim.x + threadIdx.x;
    int e = (int)(idx >> 4);
    if (e >= E) return;
    int q = ((int)idx & 15) << 2;
    int s = src[e], d = dst[e];
    const float* t = et[e] ? t1 : t0;
    float4 v = *(const float4*)&t[(long)s * 64 + q];
    float* p = &agg[(long)d * 64 + q];
    asm volatile("red.global.add.v4.f32 [%0], {%1,%2,%3,%4};"
                 :: "l"(p), "f"(v.x), "f"(v.y), "f"(v.z), "f"(v.w) : "memory");
}

// ---------------- layer 3: per-node tiny GEMMs (64 -> 2 per matrix) ----------------
__global__ void layer3_kernel(
    const float* __restrict__ H,
    const float* __restrict__ W3, const float* __restrict__ L3,
    const float* __restrict__ b3,
    float* __restrict__ e0, float* __restrict__ e1,
    float* __restrict__ out, int N)
{
    __shared__ float sW0[128], sW1[128], sL[128], sb[2];
    int tid = threadIdx.x;
    for (int i = tid; i < 128; i += blockDim.x) {
        sW0[i] = W3[i];
        sW1[i] = W3[128 + i];
        sL[i]  = L3[i];
    }
    if (tid < 2) sb[tid] = b3[tid];
    __syncthreads();

    int n = blockIdx.x * blockDim.x + tid;
    if (n >= N) return;
    const float* h = &H[(long)n * 64];
    float a0 = 0.f, a1 = 0.f, c0 = 0.f, c1 = 0.f, l0 = 0.f, l1 = 0.f;
    #pragma unroll
    for (int k = 0; k < 64; k += 4) {
        float4 hv = *(const float4*)&h[k];
        float xv[4] = {fmaxf(hv.x, 0.f), fmaxf(hv.y, 0.f),
                       fmaxf(hv.z, 0.f), fmaxf(hv.w, 0.f)};
        #pragma unroll
        for (int j = 0; j < 4; j++) {
            int kk = k + j;
            a0 = fmaf(xv[j], sW0[kk * 2 + 0], a0);
            a1 = fmaf(xv[j], sW0[kk * 2 + 1], a1);
            c0 = fmaf(xv[j], sW1[kk * 2 + 0], c0);
            c1 = fmaf(xv[j], sW1[kk * 2 + 1], c1);
            l0 = fmaf(xv[j], sL[kk * 2 + 0], l0);
            l1 = fmaf(xv[j], sL[kk * 2 + 1], l1);
        }
    }
    *(float2*)&e0[n * 2] = make_float2(a0, a1);
    *(float2*)&e1[n * 2] = make_float2(c0, c1);
    *(float2*)&out[n * 2] = make_float2(l0 + sb[0], l1 + sb[1]);
}

// ---------------- edge scatter for layer 3 (2 floats/edge) ----------------
__global__ void scatter2_kernel(
    const float* __restrict__ e0v, const float* __restrict__ e1v,
    const int* __restrict__ src, const int* __restrict__ dst,
    const int* __restrict__ et, float* __restrict__ out, int E)
{
    int e = blockIdx.x * blockDim.x + threadIdx.x;
    if (e >= E) return;
    const float* t = et[e] ? e1v : e0v;
    float2 v = *(const float2*)&t[(long)src[e] * 2];
    float* p = &out[(long)dst[e] * 2];
    asm volatile("red.global.add.v2.f32 [%0], {%1,%2};"
                 :: "l"(p), "f"(v.x), "f"(v.y) : "memory");
}

// ---------------- global min + mask ----------------
__global__ void init_min_kernel() { g_min_key = 0xFFFFFFFFu; }

__global__ void min_kernel(const float* __restrict__ v, int n)
{
    float m = 3.402823466e+38f;
    for (int i = blockIdx.x * blockDim.x + threadIdx.x; i < n;
         i += gridDim.x * blockDim.x)
        m = fminf(m, v[i]);
    #pragma unroll
    for (int o = 16; o; o >>= 1)
        m = fminf(m, __shfl_xor_sync(0xffffffffu, m, o));
    __shared__ float sm[8];
    if ((threadIdx.x & 31) == 0) sm[threadIdx.x >> 5] = m;
    __syncthreads();
    if (threadIdx.x < 8) {
        m = sm[threadIdx.x];
        #pragma unroll
        for (int o = 4; o; o >>= 1)
            m = fminf(m, __shfl_xor_sync(0xffu, m, o));
        if (threadIdx.x == 0) atomicMin(&g_min_key, fenc(m));
    }
}

__global__ void mask_kernel(float* __restrict__ out,
                            const int* __restrict__ cs,
                            const int* __restrict__ ms, int N)
{
    int n = blockIdx.x * blockDim.x + threadIdx.x;
    if (n >= N) return;
    float mn = fdec(g_min_key) - 1.0f;
    float2 v = *(float2*)&out[n * 2];
    if (cs[n] >= ms[n] - 1) v.x = mn;
    if (cs[n] == 0)         v.y = mn;
    *(float2*)&out[n * 2] = v;
}

// ---------------- launch ----------------
extern "C" void kernel_launch(void* const* d_in, const int* in_sizes, int n_in,
                              void* d_out, int out_size)
{
    const float* x  = (const float*)d_in[0];
    const int* src  = (const int*)d_in[1];
    const int* dst  = (const int*)d_in[2];
    const int* et   = (const int*)d_in[3];
    const int* cs   = (const int*)d_in[4];
    const int* ms   = (const int*)d_in[5];
    const float* W1 = (const float*)d_in[6];
    const float* L1 = (const float*)d_in[7];
    const float* b1 = (const float*)d_in[8];
    const float* W2 = (const float*)d_in[9];
    const float* L2 = (const float*)d_in[10];
    const float* b2 = (const float*)d_in[11];
    const float* W3 = (const float*)d_in[12];
    const float* L3 = (const float*)d_in[13];
    const float* b3 = (const float*)d_in[14];

    const int N = in_sizes[0] / 128;
    const int E = in_sizes[1];
    float* out = (float*)d_out;

    float *tx0, *tx1, *bufA, *bufB, *e0, *e1;
    cudaGetSymbolAddress((void**)&tx0,  g_tx0);
    cudaGetSymbolAddress((void**)&tx1,  g_tx1);
    cudaGetSymbolAddress((void**)&bufA, g_bufA);
    cudaGetSymbolAddress((void**)&bufB, g_bufB);
    cudaGetSymbolAddress((void**)&e0,   g_e0);
    cudaGetSymbolAddress((void**)&e1,   g_e1);

    // dynamic smem: (2*BM*(K+8) + 2*3*K*72) bf16 elems * 2 bytes
    constexpr int SMEM1 = (2 * 64 * (128 + 8) + 2 * 3 * 128 * 72) * 2;  // 145408
    constexpr int SMEM2 = (2 * 64 * (64 + 8)  + 2 * 3 * 64  * 72) * 2;  // 73728
    cudaFuncSetAttribute(gemm_tc_kernel<128, false>,
                         cudaFuncAttributeMaxDynamicSharedMemorySize, SMEM1);
    cudaFuncSetAttribute(gemm_tc_kernel<64, true>,
                         cudaFuncAttributeMaxDynamicSharedMemorySize, SMEM2);

    int gemmBlocks = (N + 63) / 64;
    int nodeBlocks = (N + 255) / 256;
    int scatBlocks = (E * 16 + 255) / 256;

    // layer 1: x[N,128] -> tx0/tx1/bufA[N,64]; then scatter into bufA
    gemm_tc_kernel<128, false><<<gemmBlocks, 256, SMEM1>>>(x, N,
        W1, W1 + 128 * 64, L1, b1, tx0, tx1, bufA);
    scatter64_kernel<<<scatBlocks, 256>>>(tx0, tx1, src, dst, et, bufA, E);

    // layer 2: relu(bufA)[N,64] -> tx0/tx1/bufB; then scatter into bufB
    gemm_tc_kernel<64, true><<<gemmBlocks, 256, SMEM2>>>(bufA, N,
        W2, W2 + 64 * 64, L2, b2, tx0, tx1, bufB);
    scatter64_kernel<<<scatBlocks, 256>>>(tx0, tx1, src, dst, et, bufB, E);

    // layer 3: relu(bufB) -> per-edge 2-float messages + self-loop into out
    layer3_kernel<<<nodeBlocks, 256>>>(bufB, W3, L3, b3, e0, e1, out, N);
    scatter2_kernel<<<(E + 255) / 256, 256>>>(e0, e1, src, dst, et, out, E);

    // global min then action mask
    init_min_kernel<<<1, 1>>>();
    min_kernel<<<160, 256>>>(out, N * 2);
    mask_kernel<<<nodeBlocks, 256>>>(out, cs, ms, N);
}